// round 1
// baseline (speedup 1.0000x reference)
#include <cuda_runtime.h>

#define BATCH 8
#define NTOK 4096
#define CH 64
#define NGROUP 8
#define CPG 8
#define EPSV 1e-3f

// scratch (allocation-free rule: device globals)
__device__ float g_h[BATCH * NTOK * CH];
__device__ float g_q[BATCH * NTOK * CH];
__device__ float g_k[BATCH * NTOK * CH];
__device__ float g_v[BATCH * NTOK * CH];
__device__ float g_a[BATCH * NTOK * CH];

// Store a float4 (4 consecutive c-values of row r) into a transposed tile
// T[c][r], with the r-quad XOR-swizzled by (c & 15) to avoid smem bank
// conflicts on both the scattered stores and the row-wise float4 reads.
__device__ __forceinline__ void store_T_sw(float T[64][64], int r, int cq, float4 v) {
    float vv[4] = {v.x, v.y, v.z, v.w};
    int rq = r >> 2, rl = r & 3;
#pragma unroll
    for (int s = 0; s < 4; s++) {
        int c = (cq << 2) + s;
        T[c][(((rq) ^ (c & 15)) << 2) | rl] = vv[s];
    }
}

// ---------------------------------------------------------------------------
// GroupNorm: one block per (batch, group). 4096 x 8 values per group.
// ---------------------------------------------------------------------------
__global__ void __launch_bounds__(256) gn_kernel(const float* __restrict__ x,
                                                 const float* __restrict__ gamma,
                                                 const float* __restrict__ beta) {
    int b = blockIdx.x >> 3;
    int g = blockIdx.x & 7;
    const float* xb = x + (size_t)b * NTOK * CH + g * CPG;

    float s = 0.f, s2 = 0.f;
    for (int i = threadIdx.x; i < NTOK * CPG; i += 256) {
        int n = i >> 3, j = i & 7;
        float v = xb[n * CH + j];
        s += v;
        s2 += v * v;
    }
#pragma unroll
    for (int o = 16; o > 0; o >>= 1) {
        s += __shfl_xor_sync(0xffffffffu, s, o);
        s2 += __shfl_xor_sync(0xffffffffu, s2, o);
    }
    __shared__ float sh[16];
    int wid = threadIdx.x >> 5, lid = threadIdx.x & 31;
    if (lid == 0) { sh[wid] = s; sh[8 + wid] = s2; }
    __syncthreads();
    if (threadIdx.x == 0) {
        float ts = 0.f, t2 = 0.f;
#pragma unroll
        for (int w = 0; w < 8; w++) { ts += sh[w]; t2 += sh[8 + w]; }
        float inv_n = 1.f / (float)(NTOK * CPG);
        float mean = ts * inv_n;
        float var = t2 * inv_n - mean * mean;
        sh[0] = mean;
        sh[1] = rsqrtf(var + EPSV);
    }
    __syncthreads();
    float mean = sh[0], rstd = sh[1];

    float* hb = g_h + (size_t)b * NTOK * CH + g * CPG;
    for (int i = threadIdx.x; i < NTOK * CPG; i += 256) {
        int n = i >> 3, j = i & 7;
        float v = xb[n * CH + j];
        hb[n * CH + j] = (v - mean) * rstd * gamma[g * CPG + j] + beta[g * CPG + j];
    }
}

// ---------------------------------------------------------------------------
// QKV: per block, one 64-row tile of h; three 64x64x64 GEMMs.
// 256 threads, each owns a 4x4 microtile.
// ---------------------------------------------------------------------------
__global__ void __launch_bounds__(256) qkv_kernel(const float* __restrict__ wq,
                                                  const float* __restrict__ bq,
                                                  const float* __restrict__ wk,
                                                  const float* __restrict__ bk,
                                                  const float* __restrict__ wv,
                                                  const float* __restrict__ bv) {
    __shared__ float hT[64][64];
    __shared__ float ws[64][64];
    int tid = threadIdx.x;
    int ty = tid >> 4, tx = tid & 15;
    size_t base = (size_t)blockIdx.x * 64 * CH;

    for (int f = tid; f < 1024; f += 256) {
        int r = f >> 4, cq = f & 15;
        float4 hv = *(const float4*)(g_h + base + r * CH + (cq << 2));
        store_T_sw(hT, r, cq, hv);
    }

    const float* W[3] = {wq, wk, wv};
    const float* Bv[3] = {bq, bk, bv};
    float* O[3] = {g_q, g_k, g_v};

#pragma unroll
    for (int m = 0; m < 3; m++) {
        __syncthreads();
        for (int f = tid; f < 1024; f += 256) {
            int r = f >> 4, cq = f & 15;
            *(float4*)&ws[r][cq << 2] = *(const float4*)(W[m] + r * CH + (cq << 2));
        }
        __syncthreads();
        float acc[4][4] = {};
#pragma unroll 8
        for (int c = 0; c < 64; c++) {
            float4 a = *(const float4*)&hT[c][((ty ^ (c & 15)) << 2)];
            float4 bb = *(const float4*)&ws[c][tx << 2];
            float a4[4] = {a.x, a.y, a.z, a.w};
            float b4[4] = {bb.x, bb.y, bb.z, bb.w};
#pragma unroll
            for (int i = 0; i < 4; i++)
#pragma unroll
                for (int j = 0; j < 4; j++) acc[i][j] = fmaf(a4[i], b4[j], acc[i][j]);
        }
        float4 bias = *(const float4*)(Bv[m] + (tx << 2));
        float bb4[4] = {bias.x, bias.y, bias.z, bias.w};
#pragma unroll
        for (int i = 0; i < 4; i++) {
            float4 r4;
            r4.x = acc[i][0] + bb4[0];
            r4.y = acc[i][1] + bb4[1];
            r4.z = acc[i][2] + bb4[2];
            r4.w = acc[i][3] + bb4[3];
            *(float4*)(O[m] + base + (size_t)((ty << 2) + i) * CH + (tx << 2)) = r4;
        }
    }
}

// ---------------------------------------------------------------------------
// Flash attention: one block per (batch, 64-query tile); stream 64-key tiles
// with online softmax. K-transposed buffer is reused for P-transposed so the
// three 16 KB tiles fit in exactly 48 KB static smem.
// ---------------------------------------------------------------------------
__global__ void __launch_bounds__(256) attn_kernel() {
    __shared__ float Qt[64][64];
    __shared__ float KP[64][64];
    __shared__ float Vs[64][64];

    int tid = threadIdx.x;
    int ty = tid >> 4, tx = tid & 15;
    int b = blockIdx.y;
    size_t qoff = ((size_t)b * NTOK + (size_t)blockIdx.x * 64) * CH;
    size_t kvoff = (size_t)b * NTOK * CH;

    // load Q tile transposed, pre-scaled by C^-0.5
    for (int f = tid; f < 1024; f += 256) {
        int r = f >> 4, cq = f & 15;
        float4 qv = *(const float4*)(g_q + qoff + r * CH + (cq << 2));
        qv.x *= 0.125f; qv.y *= 0.125f; qv.z *= 0.125f; qv.w *= 0.125f;
        store_T_sw(Qt, r, cq, qv);
    }

    float m[4], l[4], o[4][4];
#pragma unroll
    for (int i = 0; i < 4; i++) {
        m[i] = -1e30f;
        l[i] = 0.f;
#pragma unroll
        for (int j = 0; j < 4; j++) o[i][j] = 0.f;
    }

    for (int kt = 0; kt < 64; kt++) {
        __syncthreads();  // previous-iter KP(P) and Vs reads complete
        const float* kp = g_k + kvoff + (size_t)kt * 64 * CH;
        const float* vp = g_v + kvoff + (size_t)kt * 64 * CH;
        for (int f = tid; f < 1024; f += 256) {
            int r = f >> 4, cq = f & 15;
            float4 kv = *(const float4*)(kp + r * CH + (cq << 2));
            store_T_sw(KP, r, cq, kv);
            *(float4*)&Vs[r][cq << 2] = *(const float4*)(vp + r * CH + (cq << 2));
        }
        __syncthreads();

        // S = Q K^T  (64x64x64)
        float s[4][4] = {};
#pragma unroll 8
        for (int c = 0; c < 64; c++) {
            float4 a = *(const float4*)&Qt[c][((ty ^ (c & 15)) << 2)];
            float4 bb = *(const float4*)&KP[c][((tx ^ (c & 15)) << 2)];
            float a4[4] = {a.x, a.y, a.z, a.w};
            float b4[4] = {bb.x, bb.y, bb.z, bb.w};
#pragma unroll
            for (int i = 0; i < 4; i++)
#pragma unroll
                for (int j = 0; j < 4; j++) s[i][j] = fmaf(a4[i], b4[j], s[i][j]);
        }

        // online softmax (row groups of 16 lanes share a query row set)
#pragma unroll
        for (int i = 0; i < 4; i++) {
            float mi = fmaxf(fmaxf(s[i][0], s[i][1]), fmaxf(s[i][2], s[i][3]));
            mi = fmaxf(mi, __shfl_xor_sync(0xffffffffu, mi, 1));
            mi = fmaxf(mi, __shfl_xor_sync(0xffffffffu, mi, 2));
            mi = fmaxf(mi, __shfl_xor_sync(0xffffffffu, mi, 4));
            mi = fmaxf(mi, __shfl_xor_sync(0xffffffffu, mi, 8));
            float mn = fmaxf(m[i], mi);
            float al = __expf(m[i] - mn);
            m[i] = mn;
            float rs = 0.f;
#pragma unroll
            for (int j = 0; j < 4; j++) {
                s[i][j] = __expf(s[i][j] - mn);
                rs += s[i][j];
            }
            rs += __shfl_xor_sync(0xffffffffu, rs, 1);
            rs += __shfl_xor_sync(0xffffffffu, rs, 2);
            rs += __shfl_xor_sync(0xffffffffu, rs, 4);
            rs += __shfl_xor_sync(0xffffffffu, rs, 8);
            l[i] = l[i] * al + rs;
#pragma unroll
            for (int j = 0; j < 4; j++) o[i][j] *= al;
        }

        __syncthreads();  // everyone done reading KP as K
        // write P transposed (Pt[kj][qi]) into the KP buffer, swizzled
#pragma unroll
        for (int j = 0; j < 4; j++) {
            int kj = (tx << 2) | j;
            int col = ((ty ^ (kj & 15)) << 2);
#pragma unroll
            for (int i = 0; i < 4; i++) KP[kj][col | i] = s[i][j];
        }
        __syncthreads();

        // O += P V  (64x64x64)
#pragma unroll 8
        for (int kj = 0; kj < 64; kj++) {
            float4 p = *(const float4*)&KP[kj][((ty ^ (kj & 15)) << 2)];
            float4 vv = *(const float4*)&Vs[kj][tx << 2];
            float p4[4] = {p.x, p.y, p.z, p.w};
            float v4[4] = {vv.x, vv.y, vv.z, vv.w};
#pragma unroll
            for (int i = 0; i < 4; i++)
#pragma unroll
                for (int j = 0; j < 4; j++) o[i][j] = fmaf(p4[i], v4[j], o[i][j]);
        }
    }

    float* op = g_a + qoff;
#pragma unroll
    for (int i = 0; i < 4; i++) {
        float inv = 1.0f / l[i];
        float4 r4;
        r4.x = o[i][0] * inv;
        r4.y = o[i][1] * inv;
        r4.z = o[i][2] * inv;
        r4.w = o[i][3] * inv;
        *(float4*)(op + (size_t)((ty << 2) + i) * CH + (tx << 2)) = r4;
    }
}

// ---------------------------------------------------------------------------
// Output projection + residual: out = h + attn_out @ wp + bp
// ---------------------------------------------------------------------------
__global__ void __launch_bounds__(256) proj_kernel(const float* __restrict__ wp,
                                                   const float* __restrict__ bp,
                                                   float* __restrict__ out) {
    __shared__ float aT[64][64];
    __shared__ float ws[64][64];
    int tid = threadIdx.x;
    int ty = tid >> 4, tx = tid & 15;
    size_t base = (size_t)blockIdx.x * 64 * CH;

    for (int f = tid; f < 1024; f += 256) {
        int r = f >> 4, cq = f & 15;
        float4 av = *(const float4*)(g_a + base + r * CH + (cq << 2));
        store_T_sw(aT, r, cq, av);
        *(float4*)&ws[r][cq << 2] = *(const float4*)(wp + r * CH + (cq << 2));
    }
    __syncthreads();

    float acc[4][4] = {};
#pragma unroll 8
    for (int c = 0; c < 64; c++) {
        float4 a = *(const float4*)&aT[c][((ty ^ (c & 15)) << 2)];
        float4 bb = *(const float4*)&ws[c][tx << 2];
        float a4[4] = {a.x, a.y, a.z, a.w};
        float b4[4] = {bb.x, bb.y, bb.z, bb.w};
#pragma unroll
        for (int i = 0; i < 4; i++)
#pragma unroll
            for (int j = 0; j < 4; j++) acc[i][j] = fmaf(a4[i], b4[j], acc[i][j]);
    }

    float4 bias = *(const float4*)(bp + (tx << 2));
    float bb4[4] = {bias.x, bias.y, bias.z, bias.w};
#pragma unroll
    for (int i = 0; i < 4; i++) {
        size_t row = base + (size_t)((ty << 2) + i) * CH + (tx << 2);
        float4 h4 = *(const float4*)(g_h + row);
        float4 r4;
        r4.x = h4.x + acc[i][0] + bb4[0];
        r4.y = h4.y + acc[i][1] + bb4[1];
        r4.z = h4.z + acc[i][2] + bb4[2];
        r4.w = h4.w + acc[i][3] + bb4[3];
        *(float4*)(out + row) = r4;
    }
}

extern "C" void kernel_launch(void* const* d_in, const int* in_sizes, int n_in,
                              void* d_out, int out_size) {
    const float* x     = (const float*)d_in[0];
    const float* gamma = (const float*)d_in[1];
    const float* beta  = (const float*)d_in[2];
    const float* wq    = (const float*)d_in[3];
    const float* bq    = (const float*)d_in[4];
    const float* wk    = (const float*)d_in[5];
    const float* bk    = (const float*)d_in[6];
    const float* wv    = (const float*)d_in[7];
    const float* bv    = (const float*)d_in[8];
    const float* wp    = (const float*)d_in[9];
    const float* bp    = (const float*)d_in[10];
    float* out = (float*)d_out;

    gn_kernel<<<BATCH * NGROUP, 256>>>(x, gamma, beta);
    qkv_kernel<<<BATCH * NTOK / 64, 256>>>(wq, bq, wk, bk, wv, bv);
    attn_kernel<<<dim3(NTOK / 64, BATCH), 256>>>();
    proj_kernel<<<BATCH * NTOK / 64, 256>>>(wp, bp, out);
}

// round 2
// speedup vs baseline: 1.0870x; 1.0870x over previous
#include <cuda_runtime.h>

#define BATCH 8
#define NTOK 4096
#define CH 64
#define NGROUP 8
#define CPG 8
#define EPSV 1e-3f

typedef unsigned long long u64;

// scratch (allocation-free rule: device globals)
__device__ float g_h[BATCH * NTOK * CH];
__device__ float g_q[BATCH * NTOK * CH];
__device__ float g_k[BATCH * NTOK * CH];
__device__ float g_v[BATCH * NTOK * CH];
__device__ float g_a[BATCH * NTOK * CH];

// ---- packed f32x2 helpers (SASS FFMA2 path, PTX-only) ----
__device__ __forceinline__ u64 splat2(float x) {
    u64 r;
    asm("mov.b64 %0, {%1, %1};" : "=l"(r) : "f"(x));
    return r;
}
__device__ __forceinline__ void ffma2(u64& d, u64 a, u64 b) {
    asm("fma.rn.f32x2 %0, %1, %2, %0;" : "+l"(d) : "l"(a), "l"(b));
}
__device__ __forceinline__ u64 fmul2(u64 a, u64 b) {
    u64 r;
    asm("mul.rn.f32x2 %0, %1, %2;" : "=l"(r) : "l"(a), "l"(b));
    return r;
}
__device__ __forceinline__ float2 unpk2(u64 v) {
    float2 f;
    asm("mov.b64 {%0, %1}, %2;" : "=f"(f.x), "=f"(f.y) : "l"(v));
    return f;
}

// Store a float4 (4 consecutive c-values of row r) into a transposed tile
// T[c][r], with the r-quad XOR-swizzled by (c & 15) for conflict-free access.
__device__ __forceinline__ void store_T_sw(float T[64][64], int r, int cq, float4 v) {
    float vv[4] = {v.x, v.y, v.z, v.w};
    int rq = r >> 2, rl = r & 3;
#pragma unroll
    for (int s = 0; s < 4; s++) {
        int c = (cq << 2) + s;
        T[c][(((rq) ^ (c & 15)) << 2) | rl] = vv[s];
    }
}

// ---------------------------------------------------------------------------
// GroupNorm: one block per (batch, group). 4096 x 8 values per group.
// ---------------------------------------------------------------------------
__global__ void __launch_bounds__(256) gn_kernel(const float* __restrict__ x,
                                                 const float* __restrict__ gamma,
                                                 const float* __restrict__ beta) {
    int b = blockIdx.x >> 3;
    int g = blockIdx.x & 7;
    const float* xb = x + (size_t)b * NTOK * CH + g * CPG;

    float s = 0.f, s2 = 0.f;
    for (int i = threadIdx.x; i < NTOK * CPG; i += 256) {
        int n = i >> 3, j = i & 7;
        float v = xb[n * CH + j];
        s += v;
        s2 += v * v;
    }
#pragma unroll
    for (int o = 16; o > 0; o >>= 1) {
        s += __shfl_xor_sync(0xffffffffu, s, o);
        s2 += __shfl_xor_sync(0xffffffffu, s2, o);
    }
    __shared__ float sh[16];
    int wid = threadIdx.x >> 5, lid = threadIdx.x & 31;
    if (lid == 0) { sh[wid] = s; sh[8 + wid] = s2; }
    __syncthreads();
    if (threadIdx.x == 0) {
        float ts = 0.f, t2 = 0.f;
#pragma unroll
        for (int w = 0; w < 8; w++) { ts += sh[w]; t2 += sh[8 + w]; }
        float inv_n = 1.f / (float)(NTOK * CPG);
        float mean = ts * inv_n;
        float var = t2 * inv_n - mean * mean;
        sh[0] = mean;
        sh[1] = rsqrtf(var + EPSV);
    }
    __syncthreads();
    float mean = sh[0], rstd = sh[1];

    float* hb = g_h + (size_t)b * NTOK * CH + g * CPG;
    for (int i = threadIdx.x; i < NTOK * CPG; i += 256) {
        int n = i >> 3, j = i & 7;
        float v = xb[n * CH + j];
        hb[n * CH + j] = (v - mean) * rstd * gamma[g * CPG + j] + beta[g * CPG + j];
    }
}

// ---------------------------------------------------------------------------
// QKV: per block, one 64-row tile of h; three 64x64x64 GEMMs.
// ---------------------------------------------------------------------------
__global__ void __launch_bounds__(256) qkv_kernel(const float* __restrict__ wq,
                                                  const float* __restrict__ bq,
                                                  const float* __restrict__ wk,
                                                  const float* __restrict__ bk,
                                                  const float* __restrict__ wv,
                                                  const float* __restrict__ bv) {
    __shared__ float hT[64][64];
    __shared__ float ws[64][64];
    int tid = threadIdx.x;
    int ty = tid >> 4, tx = tid & 15;
    size_t base = (size_t)blockIdx.x * 64 * CH;

    for (int f = tid; f < 1024; f += 256) {
        int r = f >> 4, cq = f & 15;
        float4 hv = *(const float4*)(g_h + base + r * CH + (cq << 2));
        store_T_sw(hT, r, cq, hv);
    }

    const float* W[3] = {wq, wk, wv};
    const float* Bv[3] = {bq, bk, bv};
    float* O[3] = {g_q, g_k, g_v};

#pragma unroll
    for (int m = 0; m < 3; m++) {
        __syncthreads();
        for (int f = tid; f < 1024; f += 256) {
            int r = f >> 4, cq = f & 15;
            *(float4*)&ws[r][cq << 2] = *(const float4*)(W[m] + r * CH + (cq << 2));
        }
        __syncthreads();
        float acc[4][4] = {};
#pragma unroll 8
        for (int c = 0; c < 64; c++) {
            float4 a = *(const float4*)&hT[c][((ty ^ (c & 15)) << 2)];
            float4 bb = *(const float4*)&ws[c][tx << 2];
            float a4[4] = {a.x, a.y, a.z, a.w};
            float b4[4] = {bb.x, bb.y, bb.z, bb.w};
#pragma unroll
            for (int i = 0; i < 4; i++)
#pragma unroll
                for (int j = 0; j < 4; j++) acc[i][j] = fmaf(a4[i], b4[j], acc[i][j]);
        }
        float4 bias = *(const float4*)(Bv[m] + (tx << 2));
        float bb4[4] = {bias.x, bias.y, bias.z, bias.w};
#pragma unroll
        for (int i = 0; i < 4; i++) {
            float4 r4;
            r4.x = acc[i][0] + bb4[0];
            r4.y = acc[i][1] + bb4[1];
            r4.z = acc[i][2] + bb4[2];
            r4.w = acc[i][3] + bb4[3];
            *(float4*)(O[m] + base + (size_t)((ty << 2) + i) * CH + (tx << 2)) = r4;
        }
    }
}

// ---------------------------------------------------------------------------
// Flash attention, f32x2 edition. One block of 64 threads per (batch, 64-query
// tile); each thread owns an 8x8 microtile with f32x2 accumulators paired
// along the key/value (j) dimension. 48 KB static smem; KP buffer is K^T
// during QK^T and P^T during PV.
// ---------------------------------------------------------------------------
__global__ void __launch_bounds__(64) attn_kernel() {
    __shared__ float Qt[64][64];
    __shared__ float KP[64][64];
    __shared__ float Vs[64][64];

    int tid = threadIdx.x;
    int ty = tid >> 3;  // 0..7, owns rows ty*8 .. ty*8+7
    int tx = tid & 7;   // 0..7, owns cols tx*8 .. tx*8+7
    int b = blockIdx.y;
    size_t qoff = ((size_t)b * NTOK + (size_t)blockIdx.x * 64) * CH;
    size_t kvoff = (size_t)b * NTOK * CH;

    // load Q tile transposed, pre-scaled by C^-0.5
    for (int f = tid; f < 1024; f += 64) {
        int r = f >> 4, cq = f & 15;
        float4 qv = *(const float4*)(g_q + qoff + r * CH + (cq << 2));
        qv.x *= 0.125f; qv.y *= 0.125f; qv.z *= 0.125f; qv.w *= 0.125f;
        store_T_sw(Qt, r, cq, qv);
    }

    float m[8], l[8];
    u64 o2[8][4];
#pragma unroll
    for (int i = 0; i < 8; i++) {
        m[i] = -1e30f;
        l[i] = 0.f;
#pragma unroll
        for (int j = 0; j < 4; j++) o2[i][j] = 0ull;  // bit pattern = {0.f,0.f}
    }

    for (int kt = 0; kt < 64; kt++) {
        __syncthreads();  // previous-iter KP(P) and Vs reads complete
        const float* kp = g_k + kvoff + (size_t)kt * 64 * CH;
        const float* vp = g_v + kvoff + (size_t)kt * 64 * CH;
        for (int f = tid; f < 1024; f += 64) {
            int r = f >> 4, cq = f & 15;
            float4 kv = *(const float4*)(kp + r * CH + (cq << 2));
            store_T_sw(KP, r, cq, kv);
            *(float4*)&Vs[r][cq << 2] = *(const float4*)(vp + r * CH + (cq << 2));
        }
        __syncthreads();

        // ---- S = Q K^T (64x64x64), 8x8 per thread, f32x2 ----
        u64 s2[8][4];
#pragma unroll
        for (int i = 0; i < 8; i++)
#pragma unroll
            for (int j = 0; j < 4; j++) s2[i][j] = 0ull;

#pragma unroll 4
        for (int c = 0; c < 64; c++) {
            int csw = c & 15;
            float4 a0 = *(const float4*)&Qt[c][((2 * ty) ^ csw) << 2];
            float4 a1 = *(const float4*)&Qt[c][((2 * ty + 1) ^ csw) << 2];
            ulonglong2 b0 = *(const ulonglong2*)&KP[c][((2 * tx) ^ csw) << 2];
            ulonglong2 b1 = *(const ulonglong2*)&KP[c][((2 * tx + 1) ^ csw) << 2];
            u64 bv[4] = {b0.x, b0.y, b1.x, b1.y};
            float av[8] = {a0.x, a0.y, a0.z, a0.w, a1.x, a1.y, a1.z, a1.w};
#pragma unroll
            for (int i = 0; i < 8; i++) {
                u64 as = splat2(av[i]);
#pragma unroll
                for (int j = 0; j < 4; j++) ffma2(s2[i][j], as, bv[j]);
            }
        }

        // ---- online softmax over rows (8 lanes of same ty share a row) ----
        float s[8][8];
#pragma unroll
        for (int i = 0; i < 8; i++)
#pragma unroll
            for (int j = 0; j < 4; j++) {
                float2 p = unpk2(s2[i][j]);
                s[i][2 * j] = p.x;
                s[i][2 * j + 1] = p.y;
            }

#pragma unroll
        for (int i = 0; i < 8; i++) {
            float mi = s[i][0];
#pragma unroll
            for (int j = 1; j < 8; j++) mi = fmaxf(mi, s[i][j]);
            mi = fmaxf(mi, __shfl_xor_sync(0xffffffffu, mi, 1));
            mi = fmaxf(mi, __shfl_xor_sync(0xffffffffu, mi, 2));
            mi = fmaxf(mi, __shfl_xor_sync(0xffffffffu, mi, 4));
            float mn = fmaxf(m[i], mi);
            float al = __expf(m[i] - mn);
            m[i] = mn;
            float rs = 0.f;
#pragma unroll
            for (int j = 0; j < 8; j++) {
                s[i][j] = __expf(s[i][j] - mn);
                rs += s[i][j];
            }
            rs += __shfl_xor_sync(0xffffffffu, rs, 1);
            rs += __shfl_xor_sync(0xffffffffu, rs, 2);
            rs += __shfl_xor_sync(0xffffffffu, rs, 4);
            l[i] = l[i] * al + rs;
            u64 al2 = splat2(al);
#pragma unroll
            for (int j = 0; j < 4; j++) o2[i][j] = fmul2(o2[i][j], al2);
        }

        __syncthreads();  // everyone done reading KP as K
        // write P transposed (Pt[k][q]) into KP, same swizzle family
#pragma unroll
        for (int j = 0; j < 8; j++) {
            int kj = (tx << 3) | j;
            int ks = kj & 15;
            *(float4*)&KP[kj][((2 * ty) ^ ks) << 2] =
                make_float4(s[0][j], s[1][j], s[2][j], s[3][j]);
            *(float4*)&KP[kj][((2 * ty + 1) ^ ks) << 2] =
                make_float4(s[4][j], s[5][j], s[6][j], s[7][j]);
        }
        __syncthreads();

        // ---- O += P V (64x64x64), f32x2 ----
#pragma unroll 4
        for (int c = 0; c < 64; c++) {
            int csw = c & 15;
            float4 a0 = *(const float4*)&KP[c][((2 * ty) ^ csw) << 2];
            float4 a1 = *(const float4*)&KP[c][((2 * ty + 1) ^ csw) << 2];
            ulonglong2 b0 = *(const ulonglong2*)&Vs[c][(tx << 3)];
            ulonglong2 b1 = *(const ulonglong2*)&Vs[c][(tx << 3) + 4];
            u64 bv[4] = {b0.x, b0.y, b1.x, b1.y};
            float av[8] = {a0.x, a0.y, a0.z, a0.w, a1.x, a1.y, a1.z, a1.w};
#pragma unroll
            for (int i = 0; i < 8; i++) {
                u64 as = splat2(av[i]);
#pragma unroll
                for (int j = 0; j < 4; j++) ffma2(o2[i][j], as, bv[j]);
            }
        }
    }

    float* op = g_a + qoff + (size_t)(ty * 8) * CH + (tx * 8);
#pragma unroll
    for (int i = 0; i < 8; i++) {
        float inv = 1.0f / l[i];
        float r8[8];
#pragma unroll
        for (int j = 0; j < 4; j++) {
            float2 p = unpk2(o2[i][j]);
            r8[2 * j] = p.x * inv;
            r8[2 * j + 1] = p.y * inv;
        }
        *(float4*)(op + (size_t)i * CH) = make_float4(r8[0], r8[1], r8[2], r8[3]);
        *(float4*)(op + (size_t)i * CH + 4) = make_float4(r8[4], r8[5], r8[6], r8[7]);
    }
}

// ---------------------------------------------------------------------------
// Output projection + residual: out = h + attn_out @ wp + bp
// ---------------------------------------------------------------------------
__global__ void __launch_bounds__(256) proj_kernel(const float* __restrict__ wp,
                                                   const float* __restrict__ bp,
                                                   float* __restrict__ out) {
    __shared__ float aT[64][64];
    __shared__ float ws[64][64];
    int tid = threadIdx.x;
    int ty = tid >> 4, tx = tid & 15;
    size_t base = (size_t)blockIdx.x * 64 * CH;

    for (int f = tid; f < 1024; f += 256) {
        int r = f >> 4, cq = f & 15;
        float4 av = *(const float4*)(g_a + base + r * CH + (cq << 2));
        store_T_sw(aT, r, cq, av);
        *(float4*)&ws[r][cq << 2] = *(const float4*)(wp + r * CH + (cq << 2));
    }
    __syncthreads();

    float acc[4][4] = {};
#pragma unroll 8
    for (int c = 0; c < 64; c++) {
        float4 a = *(const float4*)&aT[c][((ty ^ (c & 15)) << 2)];
        float4 bb = *(const float4*)&ws[c][tx << 2];
        float a4[4] = {a.x, a.y, a.z, a.w};
        float b4[4] = {bb.x, bb.y, bb.z, bb.w};
#pragma unroll
        for (int i = 0; i < 4; i++)
#pragma unroll
            for (int j = 0; j < 4; j++) acc[i][j] = fmaf(a4[i], b4[j], acc[i][j]);
    }

    float4 bias = *(const float4*)(bp + (tx << 2));
    float bb4[4] = {bias.x, bias.y, bias.z, bias.w};
#pragma unroll
    for (int i = 0; i < 4; i++) {
        size_t row = base + (size_t)((ty << 2) + i) * CH + (tx << 2);
        float4 h4 = *(const float4*)(g_h + row);
        float4 r4;
        r4.x = h4.x + acc[i][0] + bb4[0];
        r4.y = h4.y + acc[i][1] + bb4[1];
        r4.z = h4.z + acc[i][2] + bb4[2];
        r4.w = h4.w + acc[i][3] + bb4[3];
        *(float4*)(out + row) = r4;
    }
}

extern "C" void kernel_launch(void* const* d_in, const int* in_sizes, int n_in,
                              void* d_out, int out_size) {
    const float* x     = (const float*)d_in[0];
    const float* gamma = (const float*)d_in[1];
    const float* beta  = (const float*)d_in[2];
    const float* wq    = (const float*)d_in[3];
    const float* bq    = (const float*)d_in[4];
    const float* wk    = (const float*)d_in[5];
    const float* bk    = (const float*)d_in[6];
    const float* wv    = (const float*)d_in[7];
    const float* bv    = (const float*)d_in[8];
    const float* wp    = (const float*)d_in[9];
    const float* bp    = (const float*)d_in[10];
    float* out = (float*)d_out;

    gn_kernel<<<BATCH * NGROUP, 256>>>(x, gamma, beta);
    qkv_kernel<<<BATCH * NTOK / 64, 256>>>(wq, bq, wk, bk, wv, bv);
    attn_kernel<<<dim3(NTOK / 64, BATCH), 256 / 4>>>();
    proj_kernel<<<BATCH * NTOK / 64, 256>>>(wp, bp, out);
}

// round 4
// speedup vs baseline: 6.4838x; 5.9649x over previous
#include <cuda_runtime.h>
#include <cuda_bf16.h>
#include <cstdint>

#define BATCH 8
#define NTOK 4096
#define CH 64
#define NGROUP 8
#define CPG 8
#define EPSV 1e-3f

// scratch (allocation-free rule: device globals)
__device__ float g_h[BATCH * NTOK * CH];
__device__ float g_a[BATCH * NTOK * CH];
__device__ __nv_bfloat16 g_qb[BATCH * NTOK * CH];   // Q bf16 [tok][c], pre-scaled
__device__ __nv_bfloat16 g_kb[BATCH * NTOK * CH];   // K bf16 [tok][c]
__device__ __nv_bfloat16 g_vt[BATCH * CH * NTOK];   // V^T bf16 [b][c][tok]

// ============================ PTX helpers (baseline, no 'a' features) ======
__device__ __forceinline__ uint32_t smem_u32(const void* p) {
    uint32_t a;
    asm("{ .reg .u64 t; cvta.to.shared.u64 t, %1; cvt.u32.u64 %0, t; }" : "=r"(a) : "l"(p));
    return a;
}
__device__ __forceinline__ uint32_t cvt_bf16x2(float lo, float hi) {
    uint32_t r;
    asm("cvt.rn.bf16x2.f32 %0, %1, %2;" : "=r"(r) : "f"(hi), "f"(lo));
    return r;
}
__device__ __forceinline__ void ldmx4(uint32_t& r0, uint32_t& r1, uint32_t& r2,
                                      uint32_t& r3, uint32_t addr) {
    asm volatile("ldmatrix.sync.aligned.m8n8.x4.shared.b16 {%0,%1,%2,%3}, [%4];"
                 : "=r"(r0), "=r"(r1), "=r"(r2), "=r"(r3) : "r"(addr));
}
__device__ __forceinline__ void ldmx2(uint32_t& r0, uint32_t& r1, uint32_t addr) {
    asm volatile("ldmatrix.sync.aligned.m8n8.x2.shared.b16 {%0,%1}, [%2];"
                 : "=r"(r0), "=r"(r1) : "r"(addr));
}
__device__ __forceinline__ void mma16816(float* c, uint32_t a0, uint32_t a1,
                                         uint32_t a2, uint32_t a3,
                                         uint32_t b0, uint32_t b1) {
    asm volatile(
        "mma.sync.aligned.m16n8k16.row.col.f32.bf16.bf16.f32 "
        "{%0,%1,%2,%3}, {%4,%5,%6,%7}, {%8,%9}, {%0,%1,%2,%3};"
        : "+f"(c[0]), "+f"(c[1]), "+f"(c[2]), "+f"(c[3])
        : "r"(a0), "r"(a1), "r"(a2), "r"(a3), "r"(b0), "r"(b1));
}
__device__ __forceinline__ void cpa16(uint32_t dst, const void* src) {
    asm volatile("cp.async.cg.shared.global [%0], [%1], 16;" :: "r"(dst), "l"(src)
                 : "memory");
}
#define CP_COMMIT() asm volatile("cp.async.commit_group;" ::: "memory")
#define CP_WAIT1() asm volatile("cp.async.wait_group 1;" ::: "memory")
#define CP_WAIT0() asm volatile("cp.async.wait_group 0;" ::: "memory")

// ============================ GroupNorm ============================
__global__ void __launch_bounds__(256) gn_kernel(const float* __restrict__ x,
                                                 const float* __restrict__ gamma,
                                                 const float* __restrict__ beta) {
    int b = blockIdx.x >> 3;
    int g = blockIdx.x & 7;
    const float* xb = x + (size_t)b * NTOK * CH + g * CPG;

    float s = 0.f, s2 = 0.f;
    for (int i = threadIdx.x; i < NTOK * CPG; i += 256) {
        int n = i >> 3, j = i & 7;
        float v = xb[n * CH + j];
        s += v;
        s2 += v * v;
    }
#pragma unroll
    for (int o = 16; o > 0; o >>= 1) {
        s += __shfl_xor_sync(0xffffffffu, s, o);
        s2 += __shfl_xor_sync(0xffffffffu, s2, o);
    }
    __shared__ float sh[16];
    int wid = threadIdx.x >> 5, lid = threadIdx.x & 31;
    if (lid == 0) { sh[wid] = s; sh[8 + wid] = s2; }
    __syncthreads();
    if (threadIdx.x == 0) {
        float ts = 0.f, t2 = 0.f;
#pragma unroll
        for (int w = 0; w < 8; w++) { ts += sh[w]; t2 += sh[8 + w]; }
        float inv_n = 1.f / (float)(NTOK * CPG);
        float mean = ts * inv_n;
        float var = t2 * inv_n - mean * mean;
        sh[0] = mean;
        sh[1] = rsqrtf(var + EPSV);
    }
    __syncthreads();
    float mean = sh[0], rstd = sh[1];

    float* hb = g_h + (size_t)b * NTOK * CH + g * CPG;
    for (int i = threadIdx.x; i < NTOK * CPG; i += 256) {
        int n = i >> 3, j = i & 7;
        float v = xb[n * CH + j];
        hb[n * CH + j] = (v - mean) * rstd * gamma[g * CPG + j] + beta[g * CPG + j];
    }
}

// ============================ QKV ============================
// q (scaled by C^-0.5), k -> bf16 [tok][c]; v -> bf16 transposed [b][c][tok]
__global__ void __launch_bounds__(256) qkv_kernel(const float* __restrict__ wq,
                                                  const float* __restrict__ bq,
                                                  const float* __restrict__ wk,
                                                  const float* __restrict__ bk,
                                                  const float* __restrict__ wv,
                                                  const float* __restrict__ bv) {
    __shared__ float hT[64][64];
    __shared__ float ws[64][64];
    int tid = threadIdx.x;
    int ty = tid >> 4, tx = tid & 15;
    size_t base = (size_t)blockIdx.x * 64 * CH;

    for (int f = tid; f < 1024; f += 256) {
        int r = f >> 4, cq = f & 15;
        float4 hv = *(const float4*)(g_h + base + r * CH + (cq << 2));
        float vv[4] = {hv.x, hv.y, hv.z, hv.w};
        int rq = r >> 2, rl = r & 3;
#pragma unroll
        for (int s = 0; s < 4; s++) {
            int c = (cq << 2) + s;
            hT[c][((rq ^ (c & 15)) << 2) | rl] = vv[s];
        }
    }

    const float* W[3] = {wq, wk, wv};
    const float* Bv[3] = {bq, bk, bv};

#pragma unroll
    for (int m = 0; m < 3; m++) {
        __syncthreads();
        for (int f = tid; f < 1024; f += 256) {
            int r = f >> 4, cq = f & 15;
            *(float4*)&ws[r][cq << 2] = *(const float4*)(W[m] + r * CH + (cq << 2));
        }
        __syncthreads();
        float acc[4][4] = {};
#pragma unroll 8
        for (int c = 0; c < 64; c++) {
            float4 a = *(const float4*)&hT[c][((ty ^ (c & 15)) << 2)];
            float4 bb = *(const float4*)&ws[c][tx << 2];
            float a4[4] = {a.x, a.y, a.z, a.w};
            float b4[4] = {bb.x, bb.y, bb.z, bb.w};
#pragma unroll
            for (int i = 0; i < 4; i++)
#pragma unroll
                for (int j = 0; j < 4; j++) acc[i][j] = fmaf(a4[i], b4[j], acc[i][j]);
        }
        float4 bias = *(const float4*)(Bv[m] + (tx << 2));
        float bb4[4] = {bias.x, bias.y, bias.z, bias.w};
#pragma unroll
        for (int i = 0; i < 4; i++) {
            int tok = blockIdx.x * 64 + (ty << 2) + i;
            float r4[4];
#pragma unroll
            for (int j = 0; j < 4; j++) r4[j] = acc[i][j] + bb4[j];
            if (m == 0) {
                uint32_t* o = (uint32_t*)g_qb + (size_t)tok * 32 + tx * 2;
                o[0] = cvt_bf16x2(r4[0] * 0.125f, r4[1] * 0.125f);
                o[1] = cvt_bf16x2(r4[2] * 0.125f, r4[3] * 0.125f);
            } else if (m == 1) {
                uint32_t* o = (uint32_t*)g_kb + (size_t)tok * 32 + tx * 2;
                o[0] = cvt_bf16x2(r4[0], r4[1]);
                o[1] = cvt_bf16x2(r4[2], r4[3]);
            } else {
                int b = tok >> 12, tl = tok & 4095;
#pragma unroll
                for (int j = 0; j < 4; j++)
                    g_vt[((size_t)b * CH + (tx * 4 + j)) * NTOK + tl] = __float2bfloat16(r4[j]);
            }
        }
    }
}

// ============================ Attention (mma.sync bf16) ============================
// CTA: 128 queries, 8 warps (16 rows each). Stream 64-key tiles, cp.async
// double-buffered. S and O via m16n8k16; P reused in-register as A fragments.
#define SQ_OFF 0
#define SK_OFF 16384
#define SV_OFF 32768
#define KVBUF 8192

__global__ void __launch_bounds__(256, 2) attn_kernel() {
    __shared__ __align__(16) uint8_t sm[49152];
    int tid = threadIdx.x;
    int w = tid >> 5, lane = tid & 31;
    int b = blockIdx.y, qt = blockIdx.x;
    uint32_t sb = smem_u32(sm);

    const __nv_bfloat16* gq = g_qb + ((size_t)b * NTOK + qt * 128) * CH;
    const __nv_bfloat16* gk = g_kb + (size_t)b * NTOK * CH;
    const __nv_bfloat16* gvt = g_vt + (size_t)b * CH * NTOK;

    // issue K/V tile 0
    {
        int f = tid;  // 512 chunks for K, 512 for V; 256 threads -> 2 each
#pragma unroll
        for (int u = 0; u < 2; u++, f += 256) {
            int r = f >> 3, c = f & 7;
            uint32_t sw = (uint32_t)(r * 128 + ((c ^ (r & 7)) << 4));
            cpa16(sb + SK_OFF + sw, gk + (size_t)r * CH + c * 8);
            cpa16(sb + SV_OFF + sw, gvt + (size_t)r * NTOK + c * 8);
        }
        CP_COMMIT();
    }
    // fill Q tile (swizzled [row][chunk^row])
    for (int f = tid; f < 1024; f += 256) {
        int r = f >> 3, c = f & 7;
        *(uint4*)(sm + SQ_OFF + r * 128 + ((c ^ (r & 7)) << 4)) =
            *(const uint4*)(gq + (size_t)r * CH + c * 8);
    }
    // issue tile 1
    {
        int f = tid;
#pragma unroll
        for (int u = 0; u < 2; u++, f += 256) {
            int r = f >> 3, c = f & 7;
            uint32_t sw = (uint32_t)(r * 128 + ((c ^ (r & 7)) << 4));
            cpa16(sb + SK_OFF + KVBUF + sw, gk + (size_t)(64 + r) * CH + c * 8);
            cpa16(sb + SV_OFF + KVBUF + sw, gvt + (size_t)r * NTOK + 64 + c * 8);
        }
        CP_COMMIT();
    }

    float mrow[2] = {-1e30f, -1e30f}, lrow[2] = {0.f, 0.f};
    float oc[8][4];
#pragma unroll
    for (int nt = 0; nt < 8; nt++)
#pragma unroll
        for (int j = 0; j < 4; j++) oc[nt][j] = 0.f;

    int rl = lane & 15;
    uint32_t qrowbase = sb + SQ_OFF + (uint32_t)(w * 16 + rl) * 128;
    int blrow = lane & 7;
    int blhalf = (lane >> 3) & 1;

    for (int kt = 0; kt < 64; kt++) {
        if (kt < 63) CP_WAIT1(); else CP_WAIT0();
        __syncthreads();

        uint32_t skb = sb + SK_OFF + (uint32_t)(kt & 1) * KVBUF;
        uint32_t svb = sb + SV_OFF + (uint32_t)(kt & 1) * KVBUF;

        // ---- S = Q K^T ----
        float sc[8][4];
#pragma unroll
        for (int nt = 0; nt < 8; nt++)
#pragma unroll
            for (int j = 0; j < 4; j++) sc[nt][j] = 0.f;

#pragma unroll
        for (int kk = 0; kk < 4; kk++) {
            uint32_t a0, a1, a2, a3;
            int ach = (2 * kk + (lane >> 4)) ^ (rl & 7);
            ldmx4(a0, a1, a2, a3, qrowbase + (ach << 4));
#pragma unroll
            for (int nt = 0; nt < 8; nt++) {
                int br = nt * 8 + blrow;
                int bc = (2 * kk + blhalf) ^ (br & 7);
                uint32_t b0, b1;
                ldmx2(b0, b1, skb + br * 128 + (bc << 4));
                mma16816(sc[nt], a0, a1, a2, a3, b0, b1);
            }
        }

        // ---- online softmax (rows lane/4 and lane/4+8 of warp tile) ----
        float mi0 = -1e30f, mi1 = -1e30f;
#pragma unroll
        for (int nt = 0; nt < 8; nt++) {
            mi0 = fmaxf(mi0, fmaxf(sc[nt][0], sc[nt][1]));
            mi1 = fmaxf(mi1, fmaxf(sc[nt][2], sc[nt][3]));
        }
        mi0 = fmaxf(mi0, __shfl_xor_sync(0xffffffffu, mi0, 1));
        mi0 = fmaxf(mi0, __shfl_xor_sync(0xffffffffu, mi0, 2));
        mi1 = fmaxf(mi1, __shfl_xor_sync(0xffffffffu, mi1, 1));
        mi1 = fmaxf(mi1, __shfl_xor_sync(0xffffffffu, mi1, 2));
        float mn0 = fmaxf(mrow[0], mi0), mn1 = fmaxf(mrow[1], mi1);
        float al0 = __expf(mrow[0] - mn0), al1 = __expf(mrow[1] - mn1);
        mrow[0] = mn0; mrow[1] = mn1;
        float rs0 = 0.f, rs1 = 0.f;
#pragma unroll
        for (int nt = 0; nt < 8; nt++) {
            sc[nt][0] = __expf(sc[nt][0] - mn0);
            sc[nt][1] = __expf(sc[nt][1] - mn0);
            sc[nt][2] = __expf(sc[nt][2] - mn1);
            sc[nt][3] = __expf(sc[nt][3] - mn1);
            rs0 += sc[nt][0] + sc[nt][1];
            rs1 += sc[nt][2] + sc[nt][3];
        }
        rs0 += __shfl_xor_sync(0xffffffffu, rs0, 1);
        rs0 += __shfl_xor_sync(0xffffffffu, rs0, 2);
        rs1 += __shfl_xor_sync(0xffffffffu, rs1, 1);
        rs1 += __shfl_xor_sync(0xffffffffu, rs1, 2);
        lrow[0] = lrow[0] * al0 + rs0;
        lrow[1] = lrow[1] * al1 + rs1;
#pragma unroll
        for (int nt = 0; nt < 8; nt++) {
            oc[nt][0] *= al0; oc[nt][1] *= al0;
            oc[nt][2] *= al1; oc[nt][3] *= al1;
        }

        // ---- pack P accumulators as A fragments ----
        uint32_t pf[4][4];
#pragma unroll
        for (int kk = 0; kk < 4; kk++) {
            pf[kk][0] = cvt_bf16x2(sc[2 * kk][0], sc[2 * kk][1]);
            pf[kk][1] = cvt_bf16x2(sc[2 * kk][2], sc[2 * kk][3]);
            pf[kk][2] = cvt_bf16x2(sc[2 * kk + 1][0], sc[2 * kk + 1][1]);
            pf[kk][3] = cvt_bf16x2(sc[2 * kk + 1][2], sc[2 * kk + 1][3]);
        }

        // ---- O += P V ----
#pragma unroll
        for (int kk = 0; kk < 4; kk++) {
#pragma unroll
            for (int nt = 0; nt < 8; nt++) {
                int br = nt * 8 + blrow;
                int bc = (2 * kk + blhalf) ^ (br & 7);
                uint32_t b0, b1;
                ldmx2(b0, b1, svb + br * 128 + (bc << 4));
                mma16816(oc[nt], pf[kk][0], pf[kk][1], pf[kk][2], pf[kk][3], b0, b1);
            }
        }

        __syncthreads();  // buffer (kt&1) free for refill

        if (kt + 2 < 64) {
            const __nv_bfloat16* gk2 = gk + (size_t)(kt + 2) * 64 * CH;
            const __nv_bfloat16* gvt2 = gvt + (size_t)(kt + 2) * 64;
            int f = tid;
#pragma unroll
            for (int u = 0; u < 2; u++, f += 256) {
                int r = f >> 3, c = f & 7;
                uint32_t sw = (uint32_t)(r * 128 + ((c ^ (r & 7)) << 4));
                cpa16(skb + sw, gk2 + (size_t)r * CH + c * 8);
                cpa16(svb + sw, gvt2 + (size_t)r * NTOK + c * 8);
            }
            CP_COMMIT();
        }
    }

    // epilogue: O / l -> g_a
    int r0 = qt * 128 + w * 16 + (lane >> 2);
    int cb = 2 * (lane & 3);
    float inv0 = 1.f / lrow[0], inv1 = 1.f / lrow[1];
    float* ga = g_a + (size_t)b * NTOK * CH;
#pragma unroll
    for (int nt = 0; nt < 8; nt++) {
        float2 v0 = make_float2(oc[nt][0] * inv0, oc[nt][1] * inv0);
        float2 v1 = make_float2(oc[nt][2] * inv1, oc[nt][3] * inv1);
        *(float2*)(ga + (size_t)r0 * CH + nt * 8 + cb) = v0;
        *(float2*)(ga + (size_t)(r0 + 8) * CH + nt * 8 + cb) = v1;
    }
}

// ============================ Proj + residual ============================
__global__ void __launch_bounds__(256) proj_kernel(const float* __restrict__ wp,
                                                   const float* __restrict__ bp,
                                                   float* __restrict__ out) {
    __shared__ float aT[64][64];
    __shared__ float ws[64][64];
    int tid = threadIdx.x;
    int ty = tid >> 4, tx = tid & 15;
    size_t base = (size_t)blockIdx.x * 64 * CH;

    for (int f = tid; f < 1024; f += 256) {
        int r = f >> 4, cq = f & 15;
        float4 av = *(const float4*)(g_a + base + r * CH + (cq << 2));
        float vv[4] = {av.x, av.y, av.z, av.w};
        int rq = r >> 2, rl = r & 3;
#pragma unroll
        for (int s = 0; s < 4; s++) {
            int c = (cq << 2) + s;
            aT[c][((rq ^ (c & 15)) << 2) | rl] = vv[s];
        }
        *(float4*)&ws[r][cq << 2] = *(const float4*)(wp + r * CH + (cq << 2));
    }
    __syncthreads();

    float acc[4][4] = {};
#pragma unroll 8
    for (int c = 0; c < 64; c++) {
        float4 a = *(const float4*)&aT[c][((ty ^ (c & 15)) << 2)];
        float4 bb = *(const float4*)&ws[c][tx << 2];
        float a4[4] = {a.x, a.y, a.z, a.w};
        float b4[4] = {bb.x, bb.y, bb.z, bb.w};
#pragma unroll
        for (int i = 0; i < 4; i++)
#pragma unroll
            for (int j = 0; j < 4; j++) acc[i][j] = fmaf(a4[i], b4[j], acc[i][j]);
    }

    float4 bias = *(const float4*)(bp + (tx << 2));
    float bb4[4] = {bias.x, bias.y, bias.z, bias.w};
#pragma unroll
    for (int i = 0; i < 4; i++) {
        size_t row = base + (size_t)((ty << 2) + i) * CH + (tx << 2);
        float4 h4 = *(const float4*)(g_h + row);
        float4 r4;
        r4.x = h4.x + acc[i][0] + bb4[0];
        r4.y = h4.y + acc[i][1] + bb4[1];
        r4.z = h4.z + acc[i][2] + bb4[2];
        r4.w = h4.w + acc[i][3] + bb4[3];
        *(float4*)(out + row) = r4;
    }
}

extern "C" void kernel_launch(void* const* d_in, const int* in_sizes, int n_in,
                              void* d_out, int out_size) {
    const float* x     = (const float*)d_in[0];
    const float* gamma = (const float*)d_in[1];
    const float* beta  = (const float*)d_in[2];
    const float* wq    = (const float*)d_in[3];
    const float* bq    = (const float*)d_in[4];
    const float* wk    = (const float*)d_in[5];
    const float* bk    = (const float*)d_in[6];
    const float* wv    = (const float*)d_in[7];
    const float* bv    = (const float*)d_in[8];
    const float* wp    = (const float*)d_in[9];
    const float* bp    = (const float*)d_in[10];
    float* out = (float*)d_out;

    gn_kernel<<<BATCH * NGROUP, 256>>>(x, gamma, beta);
    qkv_kernel<<<BATCH * NTOK / 64, 256>>>(wq, bq, wk, bk, wv, bv);
    attn_kernel<<<dim3(NTOK / 128, BATCH), 256>>>();
    proj_kernel<<<BATCH * NTOK / 64, 256>>>(wp, bp, out);
}

// round 5
// speedup vs baseline: 6.9958x; 1.0790x over previous
#include <cuda_runtime.h>
#include <cuda_bf16.h>
#include <cstdint>

#define BATCH 8
#define NTOK 4096
#define CH 64
#define NGROUP 8
#define CPG 8
#define EPSV 1e-3f

// Q pre-scale: C^-0.5 * log2(e), so softmax runs in base-2 (exp2f = bare MUFU)
#define QSCALE 0.1803368801111204f

// scratch (allocation-free rule: device globals)
__device__ float g_h[BATCH * NTOK * CH];
__device__ float g_a[BATCH * NTOK * CH];
__device__ __nv_bfloat16 g_qb[BATCH * NTOK * CH];   // Q bf16 [tok][c], pre-scaled
__device__ __nv_bfloat16 g_kb[BATCH * NTOK * CH];   // K bf16 [tok][c]
__device__ __nv_bfloat16 g_vt[BATCH * CH * NTOK];   // V^T bf16 [b][c][tok]

// ============================ PTX helpers (baseline, no 'a' features) ======
__device__ __forceinline__ uint32_t smem_u32(const void* p) {
    uint32_t a;
    asm("{ .reg .u64 t; cvta.to.shared.u64 t, %1; cvt.u32.u64 %0, t; }" : "=r"(a) : "l"(p));
    return a;
}
__device__ __forceinline__ uint32_t cvt_bf16x2(float lo, float hi) {
    uint32_t r;
    asm("cvt.rn.bf16x2.f32 %0, %1, %2;" : "=r"(r) : "f"(hi), "f"(lo));
    return r;
}
__device__ __forceinline__ void ldmx4(uint32_t& r0, uint32_t& r1, uint32_t& r2,
                                      uint32_t& r3, uint32_t addr) {
    asm volatile("ldmatrix.sync.aligned.m8n8.x4.shared.b16 {%0,%1,%2,%3}, [%4];"
                 : "=r"(r0), "=r"(r1), "=r"(r2), "=r"(r3) : "r"(addr));
}
__device__ __forceinline__ void ldmx2(uint32_t& r0, uint32_t& r1, uint32_t addr) {
    asm volatile("ldmatrix.sync.aligned.m8n8.x2.shared.b16 {%0,%1}, [%2];"
                 : "=r"(r0), "=r"(r1) : "r"(addr));
}
__device__ __forceinline__ void mma16816(float* c, uint32_t a0, uint32_t a1,
                                         uint32_t a2, uint32_t a3,
                                         uint32_t b0, uint32_t b1) {
    asm volatile(
        "mma.sync.aligned.m16n8k16.row.col.f32.bf16.bf16.f32 "
        "{%0,%1,%2,%3}, {%4,%5,%6,%7}, {%8,%9}, {%0,%1,%2,%3};"
        : "+f"(c[0]), "+f"(c[1]), "+f"(c[2]), "+f"(c[3])
        : "r"(a0), "r"(a1), "r"(a2), "r"(a3), "r"(b0), "r"(b1));
}
__device__ __forceinline__ void cpa16(uint32_t dst, const void* src) {
    asm volatile("cp.async.cg.shared.global [%0], [%1], 16;" :: "r"(dst), "l"(src)
                 : "memory");
}
#define CP_COMMIT() asm volatile("cp.async.commit_group;" ::: "memory")
#define CP_WAIT1() asm volatile("cp.async.wait_group 1;" ::: "memory")
#define CP_WAIT0() asm volatile("cp.async.wait_group 0;" ::: "memory")

// ============================ GroupNorm ============================
__global__ void __launch_bounds__(256) gn_kernel(const float* __restrict__ x,
                                                 const float* __restrict__ gamma,
                                                 const float* __restrict__ beta) {
    int b = blockIdx.x >> 3;
    int g = blockIdx.x & 7;
    const float* xb = x + (size_t)b * NTOK * CH + g * CPG;

    float s = 0.f, s2 = 0.f;
    for (int i = threadIdx.x; i < NTOK * CPG; i += 256) {
        int n = i >> 3, j = i & 7;
        float v = xb[n * CH + j];
        s += v;
        s2 += v * v;
    }
#pragma unroll
    for (int o = 16; o > 0; o >>= 1) {
        s += __shfl_xor_sync(0xffffffffu, s, o);
        s2 += __shfl_xor_sync(0xffffffffu, s2, o);
    }
    __shared__ float sh[16];
    int wid = threadIdx.x >> 5, lid = threadIdx.x & 31;
    if (lid == 0) { sh[wid] = s; sh[8 + wid] = s2; }
    __syncthreads();
    if (threadIdx.x == 0) {
        float ts = 0.f, t2 = 0.f;
#pragma unroll
        for (int w = 0; w < 8; w++) { ts += sh[w]; t2 += sh[8 + w]; }
        float inv_n = 1.f / (float)(NTOK * CPG);
        float mean = ts * inv_n;
        float var = t2 * inv_n - mean * mean;
        sh[0] = mean;
        sh[1] = rsqrtf(var + EPSV);
    }
    __syncthreads();
    float mean = sh[0], rstd = sh[1];

    float* hb = g_h + (size_t)b * NTOK * CH + g * CPG;
    for (int i = threadIdx.x; i < NTOK * CPG; i += 256) {
        int n = i >> 3, j = i & 7;
        float v = xb[n * CH + j];
        hb[n * CH + j] = (v - mean) * rstd * gamma[g * CPG + j] + beta[g * CPG + j];
    }
}

// ============================ QKV ============================
// q (scaled by QSCALE), k -> bf16 [tok][c]; v -> bf16 transposed [b][c][tok]
__global__ void __launch_bounds__(256) qkv_kernel(const float* __restrict__ wq,
                                                  const float* __restrict__ bq,
                                                  const float* __restrict__ wk,
                                                  const float* __restrict__ bk,
                                                  const float* __restrict__ wv,
                                                  const float* __restrict__ bv) {
    __shared__ float hT[64][64];
    __shared__ float ws[64][64];
    int tid = threadIdx.x;
    int ty = tid >> 4, tx = tid & 15;
    size_t base = (size_t)blockIdx.x * 64 * CH;

    for (int f = tid; f < 1024; f += 256) {
        int r = f >> 4, cq = f & 15;
        float4 hv = *(const float4*)(g_h + base + r * CH + (cq << 2));
        float vv[4] = {hv.x, hv.y, hv.z, hv.w};
        int rq = r >> 2, rl = r & 3;
#pragma unroll
        for (int s = 0; s < 4; s++) {
            int c = (cq << 2) + s;
            hT[c][((rq ^ (c & 15)) << 2) | rl] = vv[s];
        }
    }

    const float* W[3] = {wq, wk, wv};
    const float* Bv[3] = {bq, bk, bv};

#pragma unroll
    for (int m = 0; m < 3; m++) {
        __syncthreads();
        for (int f = tid; f < 1024; f += 256) {
            int r = f >> 4, cq = f & 15;
            *(float4*)&ws[r][cq << 2] = *(const float4*)(W[m] + r * CH + (cq << 2));
        }
        __syncthreads();
        float acc[4][4] = {};
#pragma unroll 8
        for (int c = 0; c < 64; c++) {
            float4 a = *(const float4*)&hT[c][((ty ^ (c & 15)) << 2)];
            float4 bb = *(const float4*)&ws[c][tx << 2];
            float a4[4] = {a.x, a.y, a.z, a.w};
            float b4[4] = {bb.x, bb.y, bb.z, bb.w};
#pragma unroll
            for (int i = 0; i < 4; i++)
#pragma unroll
                for (int j = 0; j < 4; j++) acc[i][j] = fmaf(a4[i], b4[j], acc[i][j]);
        }
        float4 bias = *(const float4*)(Bv[m] + (tx << 2));
        float bb4[4] = {bias.x, bias.y, bias.z, bias.w};
#pragma unroll
        for (int i = 0; i < 4; i++) {
            int tok = blockIdx.x * 64 + (ty << 2) + i;
            float r4[4];
#pragma unroll
            for (int j = 0; j < 4; j++) r4[j] = acc[i][j] + bb4[j];
            if (m == 0) {
                uint32_t* o = (uint32_t*)g_qb + (size_t)tok * 32 + tx * 2;
                o[0] = cvt_bf16x2(r4[0] * QSCALE, r4[1] * QSCALE);
                o[1] = cvt_bf16x2(r4[2] * QSCALE, r4[3] * QSCALE);
            } else if (m == 1) {
                uint32_t* o = (uint32_t*)g_kb + (size_t)tok * 32 + tx * 2;
                o[0] = cvt_bf16x2(r4[0], r4[1]);
                o[1] = cvt_bf16x2(r4[2], r4[3]);
            } else {
                int b = tok >> 12, tl = tok & 4095;
#pragma unroll
                for (int j = 0; j < 4; j++)
                    g_vt[((size_t)b * CH + (tx * 4 + j)) * NTOK + tl] = __float2bfloat16(r4[j]);
            }
        }
    }
}

// ============================ Attention (mma.sync bf16) ============================
// CTA: 128 queries, 4 warps x 32 rows (two m16 A-tiles per warp) so each
// ldmatrix B fragment feeds two MMAs. Stream 64-key tiles double-buffered.
#define SQ_OFF 0
#define SK_OFF 16384
#define SV_OFF 32768
#define KVBUF 8192

__global__ void __launch_bounds__(128, 2) attn_kernel() {
    __shared__ __align__(16) uint8_t sm[49152];
    int tid = threadIdx.x;
    int w = tid >> 5, lane = tid & 31;
    int b = blockIdx.y, qt = blockIdx.x;
    uint32_t sb = smem_u32(sm);

    const __nv_bfloat16* gq = g_qb + ((size_t)b * NTOK + qt * 128) * CH;
    const __nv_bfloat16* gk = g_kb + (size_t)b * NTOK * CH;
    const __nv_bfloat16* gvt = g_vt + (size_t)b * CH * NTOK;

    // issue K/V tile 0 (512 chunks each; 128 threads -> 4 per thread per tensor)
    {
        int f = tid;
#pragma unroll
        for (int u = 0; u < 4; u++, f += 128) {
            int r = f >> 3, c = f & 7;
            uint32_t sw = (uint32_t)(r * 128 + ((c ^ (r & 7)) << 4));
            cpa16(sb + SK_OFF + sw, gk + (size_t)r * CH + c * 8);
            cpa16(sb + SV_OFF + sw, gvt + (size_t)r * NTOK + c * 8);
        }
        CP_COMMIT();
    }
    // fill Q tile (swizzled [row][chunk^row])
    for (int f = tid; f < 1024; f += 128) {
        int r = f >> 3, c = f & 7;
        *(uint4*)(sm + SQ_OFF + r * 128 + ((c ^ (r & 7)) << 4)) =
            *(const uint4*)(gq + (size_t)r * CH + c * 8);
    }
    // issue tile 1
    {
        int f = tid;
#pragma unroll
        for (int u = 0; u < 4; u++, f += 128) {
            int r = f >> 3, c = f & 7;
            uint32_t sw = (uint32_t)(r * 128 + ((c ^ (r & 7)) << 4));
            cpa16(sb + SK_OFF + KVBUF + sw, gk + (size_t)(64 + r) * CH + c * 8);
            cpa16(sb + SV_OFF + KVBUF + sw, gvt + (size_t)r * NTOK + 64 + c * 8);
        }
        CP_COMMIT();
    }

    float mrow[2][2], lrow[2][2];
    float oc[2][8][4];
#pragma unroll
    for (int mt = 0; mt < 2; mt++) {
        mrow[mt][0] = mrow[mt][1] = -1e30f;
        lrow[mt][0] = lrow[mt][1] = 0.f;
#pragma unroll
        for (int nt = 0; nt < 8; nt++)
#pragma unroll
            for (int j = 0; j < 4; j++) oc[mt][nt][j] = 0.f;
    }

    int rl = lane & 15;
    uint32_t qbase0 = sb + SQ_OFF + (uint32_t)(w * 32 + rl) * 128;
    uint32_t qbase1 = qbase0 + 16 * 128;
    int blrow = lane & 7;
    int blhalf = (lane >> 3) & 1;

    for (int kt = 0; kt < 64; kt++) {
        if (kt < 63) CP_WAIT1(); else CP_WAIT0();
        __syncthreads();

        uint32_t skb = sb + SK_OFF + (uint32_t)(kt & 1) * KVBUF;
        uint32_t svb = sb + SV_OFF + (uint32_t)(kt & 1) * KVBUF;

        // ---- S = Q K^T (two m-tiles per warp) ----
        float sc[2][8][4];
#pragma unroll
        for (int mt = 0; mt < 2; mt++)
#pragma unroll
            for (int nt = 0; nt < 8; nt++)
#pragma unroll
                for (int j = 0; j < 4; j++) sc[mt][nt][j] = 0.f;

#pragma unroll
        for (int kk = 0; kk < 4; kk++) {
            uint32_t a0[4], a1[4];
            int ach = (2 * kk + (lane >> 4)) ^ (rl & 7);
            ldmx4(a0[0], a0[1], a0[2], a0[3], qbase0 + (ach << 4));
            ldmx4(a1[0], a1[1], a1[2], a1[3], qbase1 + (ach << 4));
#pragma unroll
            for (int nt = 0; nt < 8; nt++) {
                int br = nt * 8 + blrow;
                int bc = (2 * kk + blhalf) ^ (br & 7);
                uint32_t b0, b1;
                ldmx2(b0, b1, skb + br * 128 + (bc << 4));
                mma16816(sc[0][nt], a0[0], a0[1], a0[2], a0[3], b0, b1);
                mma16816(sc[1][nt], a1[0], a1[1], a1[2], a1[3], b0, b1);
            }
        }

        // ---- online softmax (base-2 domain) ----
        float al[2][2];
#pragma unroll
        for (int mt = 0; mt < 2; mt++) {
            float mi0 = -1e30f, mi1 = -1e30f;
#pragma unroll
            for (int nt = 0; nt < 8; nt++) {
                mi0 = fmaxf(mi0, fmaxf(sc[mt][nt][0], sc[mt][nt][1]));
                mi1 = fmaxf(mi1, fmaxf(sc[mt][nt][2], sc[mt][nt][3]));
            }
            mi0 = fmaxf(mi0, __shfl_xor_sync(0xffffffffu, mi0, 1));
            mi0 = fmaxf(mi0, __shfl_xor_sync(0xffffffffu, mi0, 2));
            mi1 = fmaxf(mi1, __shfl_xor_sync(0xffffffffu, mi1, 1));
            mi1 = fmaxf(mi1, __shfl_xor_sync(0xffffffffu, mi1, 2));
            float mn0 = fmaxf(mrow[mt][0], mi0), mn1 = fmaxf(mrow[mt][1], mi1);
            al[mt][0] = exp2f(mrow[mt][0] - mn0);
            al[mt][1] = exp2f(mrow[mt][1] - mn1);
            mrow[mt][0] = mn0; mrow[mt][1] = mn1;
            float rs0 = 0.f, rs1 = 0.f;
#pragma unroll
            for (int nt = 0; nt < 8; nt++) {
                sc[mt][nt][0] = exp2f(sc[mt][nt][0] - mn0);
                sc[mt][nt][1] = exp2f(sc[mt][nt][1] - mn0);
                sc[mt][nt][2] = exp2f(sc[mt][nt][2] - mn1);
                sc[mt][nt][3] = exp2f(sc[mt][nt][3] - mn1);
                rs0 += sc[mt][nt][0] + sc[mt][nt][1];
                rs1 += sc[mt][nt][2] + sc[mt][nt][3];
            }
            rs0 += __shfl_xor_sync(0xffffffffu, rs0, 1);
            rs0 += __shfl_xor_sync(0xffffffffu, rs0, 2);
            rs1 += __shfl_xor_sync(0xffffffffu, rs1, 1);
            rs1 += __shfl_xor_sync(0xffffffffu, rs1, 2);
            lrow[mt][0] = lrow[mt][0] * al[mt][0] + rs0;
            lrow[mt][1] = lrow[mt][1] * al[mt][1] + rs1;
#pragma unroll
            for (int nt = 0; nt < 8; nt++) {
                oc[mt][nt][0] *= al[mt][0]; oc[mt][nt][1] *= al[mt][0];
                oc[mt][nt][2] *= al[mt][1]; oc[mt][nt][3] *= al[mt][1];
            }
        }

        // ---- O += P V (pack P per kk, reuse B for both m-tiles) ----
#pragma unroll
        for (int kk = 0; kk < 4; kk++) {
            uint32_t pf0[4], pf1[4];
            pf0[0] = cvt_bf16x2(sc[0][2 * kk][0], sc[0][2 * kk][1]);
            pf0[1] = cvt_bf16x2(sc[0][2 * kk][2], sc[0][2 * kk][3]);
            pf0[2] = cvt_bf16x2(sc[0][2 * kk + 1][0], sc[0][2 * kk + 1][1]);
            pf0[3] = cvt_bf16x2(sc[0][2 * kk + 1][2], sc[0][2 * kk + 1][3]);
            pf1[0] = cvt_bf16x2(sc[1][2 * kk][0], sc[1][2 * kk][1]);
            pf1[1] = cvt_bf16x2(sc[1][2 * kk][2], sc[1][2 * kk][3]);
            pf1[2] = cvt_bf16x2(sc[1][2 * kk + 1][0], sc[1][2 * kk + 1][1]);
            pf1[3] = cvt_bf16x2(sc[1][2 * kk + 1][2], sc[1][2 * kk + 1][3]);
#pragma unroll
            for (int nt = 0; nt < 8; nt++) {
                int br = nt * 8 + blrow;
                int bc = (2 * kk + blhalf) ^ (br & 7);
                uint32_t b0, b1;
                ldmx2(b0, b1, svb + br * 128 + (bc << 4));
                mma16816(oc[0][nt], pf0[0], pf0[1], pf0[2], pf0[3], b0, b1);
                mma16816(oc[1][nt], pf1[0], pf1[1], pf1[2], pf1[3], b0, b1);
            }
        }

        __syncthreads();  // buffer (kt&1) free for refill

        if (kt + 2 < 64) {
            const __nv_bfloat16* gk2 = gk + (size_t)(kt + 2) * 64 * CH;
            const __nv_bfloat16* gvt2 = gvt + (size_t)(kt + 2) * 64;
            int f = tid;
#pragma unroll
            for (int u = 0; u < 4; u++, f += 128) {
                int r = f >> 3, c = f & 7;
                uint32_t sw = (uint32_t)(r * 128 + ((c ^ (r & 7)) << 4));
                cpa16(skb + sw, gk2 + (size_t)r * CH + c * 8);
                cpa16(svb + sw, gvt2 + (size_t)r * NTOK + c * 8);
            }
            CP_COMMIT();
        }
    }

    // epilogue: O / l -> g_a
    float* ga = g_a + (size_t)b * NTOK * CH;
    int cb = 2 * (lane & 3);
#pragma unroll
    for (int mt = 0; mt < 2; mt++) {
        int r0 = qt * 128 + w * 32 + mt * 16 + (lane >> 2);
        float inv0 = 1.f / lrow[mt][0], inv1 = 1.f / lrow[mt][1];
#pragma unroll
        for (int nt = 0; nt < 8; nt++) {
            float2 v0 = make_float2(oc[mt][nt][0] * inv0, oc[mt][nt][1] * inv0);
            float2 v1 = make_float2(oc[mt][nt][2] * inv1, oc[mt][nt][3] * inv1);
            *(float2*)(ga + (size_t)r0 * CH + nt * 8 + cb) = v0;
            *(float2*)(ga + (size_t)(r0 + 8) * CH + nt * 8 + cb) = v1;
        }
    }
}

// ============================ Proj + residual ============================
__global__ void __launch_bounds__(256) proj_kernel(const float* __restrict__ wp,
                                                   const float* __restrict__ bp,
                                                   float* __restrict__ out) {
    __shared__ float aT[64][64];
    __shared__ float ws[64][64];
    int tid = threadIdx.x;
    int ty = tid >> 4, tx = tid & 15;
    size_t base = (size_t)blockIdx.x * 64 * CH;

    for (int f = tid; f < 1024; f += 256) {
        int r = f >> 4, cq = f & 15;
        float4 av = *(const float4*)(g_a + base + r * CH + (cq << 2));
        float vv[4] = {av.x, av.y, av.z, av.w};
        int rq = r >> 2, rl = r & 3;
#pragma unroll
        for (int s = 0; s < 4; s++) {
            int c = (cq << 2) + s;
            aT[c][((rq ^ (c & 15)) << 2) | rl] = vv[s];
        }
        *(float4*)&ws[r][cq << 2] = *(const float4*)(wp + r * CH + (cq << 2));
    }
    __syncthreads();

    float acc[4][4] = {};
#pragma unroll 8
    for (int c = 0; c < 64; c++) {
        float4 a = *(const float4*)&aT[c][((ty ^ (c & 15)) << 2)];
        float4 bb = *(const float4*)&ws[c][tx << 2];
        float a4[4] = {a.x, a.y, a.z, a.w};
        float b4[4] = {bb.x, bb.y, bb.z, bb.w};
#pragma unroll
        for (int i = 0; i < 4; i++)
#pragma unroll
            for (int j = 0; j < 4; j++) acc[i][j] = fmaf(a4[i], b4[j], acc[i][j]);
    }

    float4 bias = *(const float4*)(bp + (tx << 2));
    float bb4[4] = {bias.x, bias.y, bias.z, bias.w};
#pragma unroll
    for (int i = 0; i < 4; i++) {
        size_t row = base + (size_t)((ty << 2) + i) * CH + (tx << 2);
        float4 h4 = *(const float4*)(g_h + row);
        float4 r4;
        r4.x = h4.x + acc[i][0] + bb4[0];
        r4.y = h4.y + acc[i][1] + bb4[1];
        r4.z = h4.z + acc[i][2] + bb4[2];
        r4.w = h4.w + acc[i][3] + bb4[3];
        *(float4*)(out + row) = r4;
    }
}

extern "C" void kernel_launch(void* const* d_in, const int* in_sizes, int n_in,
                              void* d_out, int out_size) {
    const float* x     = (const float*)d_in[0];
    const float* gamma = (const float*)d_in[1];
    const float* beta  = (const float*)d_in[2];
    const float* wq    = (const float*)d_in[3];
    const float* bq    = (const float*)d_in[4];
    const float* wk    = (const float*)d_in[5];
    const float* bk    = (const float*)d_in[6];
    const float* wv    = (const float*)d_in[7];
    const float* bv    = (const float*)d_in[8];
    const float* wp    = (const float*)d_in[9];
    const float* bp    = (const float*)d_in[10];
    float* out = (float*)d_out;

    gn_kernel<<<BATCH * NGROUP, 256>>>(x, gamma, beta);
    qkv_kernel<<<BATCH * NTOK / 64, 256>>>(wq, bq, wk, bk, wv, bv);
    attn_kernel<<<dim3(NTOK / 128, BATCH), 128>>>();
    proj_kernel<<<BATCH * NTOK / 64, 256>>>(wp, bp, out);
}